// round 16
// baseline (speedup 1.0000x reference)
#include <cuda_runtime.h>
#include <cuda_fp16.h>

#define NN      4096
#define HEADS   8
#define OUT_F   64
#define ITILE   128
#define VPITCH  72     // halfs per sV row (144B)

__device__ __half   g_V[(size_t)HEADS * NN * OUT_F];
__device__ __half   g_gsh [HEADS * NN];
__device__ __half   g_EDh [HEADS * NN];
__device__ __half   g_FDh [HEADS * NN];
__device__ unsigned g_adjbits[NN * (NN / 32)];
__device__ __half   g_hph[(size_t)NN * 512];
__device__ int      g_cnt[NN / ITILE];   // zero-init; reset by last CTA each run

__device__ __forceinline__ void cp16(unsigned dst, const void* src) {
    asm volatile("cp.async.cg.shared.global [%0], [%1], 16;"
                 :: "r"(dst), "l"(__cvta_generic_to_global(src)));
}
__device__ __forceinline__ __half2 u2h2(unsigned x) { return *reinterpret_cast<__half2*>(&x); }
__device__ __forceinline__ unsigned h22u(__half2 x) { return *reinterpret_cast<unsigned*>(&x); }
// 2 adjacency bits -> half2 keep-mask
__device__ __forceinline__ unsigned bmask(unsigned b) {
    return ((b & 1u) * 0xFFFFu) | ((b & 2u) * 0x7FFF8000u);
}
// w = adj ? max(ed, gs*fd) : 0   (lrelu(x)=max(x,0.2x) => exp factorization)
__device__ __forceinline__ unsigned wval(unsigned ed, __half2 gs, __half2 fd, unsigned am) {
    return h22u(__hmax2(u2h2(ed), __hmul2(gs, fd))) & am;
}
__device__ __forceinline__ void mma16816(float* c, unsigned a0, unsigned a1,
                                         unsigned a2, unsigned a3,
                                         unsigned b0, unsigned b1) {
    asm volatile("mma.sync.aligned.m16n8k16.row.col.f32.f16.f16.f32 "
                 "{%0,%1,%2,%3}, {%4,%5,%6,%7}, {%8,%9}, {%0,%1,%2,%3};\n"
                 : "+f"(c[0]), "+f"(c[1]), "+f"(c[2]), "+f"(c[3])
                 : "r"(a0), "r"(a1), "r"(a2), "r"(a3), "r"(b0), "r"(b1));
}

// ---------------- K0: pack adjacency into bitmask (runs on side stream) ----------------
__global__ void k_pack_adj(const int* __restrict__ adj) {
    int idx = blockIdx.x * blockDim.x + threadIdx.x;
    int v = adj[idx];
    unsigned m = __ballot_sync(0xffffffffu, v > 0);
    if ((threadIdx.x & 31) == 0) g_adjbits[idx >> 5] = m;
}

// ---------------- K1: ht = h @ W (fp16 TC, in-kernel fp32->fp16 convert) ----------------
__global__ __launch_bounds__(256) void k_gemm_ht(const float* __restrict__ hmat,
                                                 const float* __restrict__ W,
                                                 const float* __restrict__ avec) {
    __shared__ __align__(16) __half sA[128 * 72];
    __shared__ __align__(16) __half sB[64 * 72];
    const int t = threadIdx.x, lane = t & 31, wid = t >> 5;
    const int head = blockIdx.x, rowBase = blockIdx.y * 128;
    const int l15 = lane & 15, lhi = (lane >> 4) << 3, qc = (lane & 3) << 1;
    const unsigned sAb = (unsigned)__cvta_generic_to_shared(sA);
    const unsigned sBb = (unsigned)__cvta_generic_to_shared(sB);
    const int arow = t >> 1, ahalf = t & 1;

    float4 pa[8], pb[8];
    auto ldg_stage = [&](int k0) {
        const float4* src = (const float4*)(hmat + (size_t)(rowBase + arow) * 256 + k0 + ahalf * 32);
#pragma unroll
        for (int i = 0; i < 8; i++) pa[i] = src[i];
        if (t < 128) {
            const float4* bs = (const float4*)(W + (size_t)(k0 + arow) * 512 + head * 64 + ahalf * 32);
#pragma unroll
            for (int i = 0; i < 8; i++) pb[i] = bs[i];
        }
    };
    auto sts_stage = [&]() {
        __half* da = sA + arow * 72 + ahalf * 32;
#pragma unroll
        for (int i = 0; i < 8; i++) {
            *(__half2*)(da + i * 4)     = __floats2half2_rn(pa[i].x, pa[i].y);
            *(__half2*)(da + i * 4 + 2) = __floats2half2_rn(pa[i].z, pa[i].w);
        }
        if (t < 128) {
            __half* db = sB + arow * 72 + ahalf * 32;
#pragma unroll
            for (int i = 0; i < 8; i++) {
                *(__half2*)(db + i * 4)     = __floats2half2_rn(pb[i].x, pb[i].y);
                *(__half2*)(db + i * 4 + 2) = __floats2half2_rn(pb[i].z, pb[i].w);
            }
        }
    };

    float acc[8][4];
#pragma unroll
    for (int x = 0; x < 8; x++)
#pragma unroll
        for (int y = 0; y < 4; y++) acc[x][y] = 0.f;

    ldg_stage(0);
    for (int s = 0; s < 4; ++s) {
        sts_stage();
        __syncthreads();
        if (s < 3) ldg_stage((s + 1) * 64);   // overlap next LDG with this stage's mma
#pragma unroll
        for (int kt = 0; kt < 4; ++kt) {
            unsigned a0, a1, a2, a3;
            unsigned aAddr = sAb + (((wid << 4) + l15) * 72 + (kt << 4) + lhi) * 2;
            asm volatile("ldmatrix.sync.aligned.m8n8.x4.shared.b16 {%0,%1,%2,%3}, [%4];\n"
                         : "=r"(a0), "=r"(a1), "=r"(a2), "=r"(a3) : "r"(aAddr));
#pragma unroll
            for (int ng = 0; ng < 4; ++ng) {
                unsigned b0, b1, b2, b3;
                unsigned bAddr = sBb + (((kt << 4) + l15) * 72 + (ng << 4) + lhi) * 2;
                asm volatile("ldmatrix.sync.aligned.m8n8.x4.trans.shared.b16 {%0,%1,%2,%3}, [%4];\n"
                             : "=r"(b0), "=r"(b1), "=r"(b2), "=r"(b3) : "r"(bAddr));
                mma16816(acc[2 * ng],     a0, a1, a2, a3, b0, b1);
                mma16816(acc[2 * ng + 1], a0, a1, a2, a3, b2, b3);
            }
        }
        __syncthreads();
    }
    const int r = rowBase + (wid << 4) + (lane >> 2);
    __half* vp = g_V + (size_t)head * NN * 64 + (size_t)r * 64;
#pragma unroll
    for (int ng = 0; ng < 4; ++ng) {
        int c0 = ng * 16 + qc;
        *(__half2*)(vp + c0)            = __floats2half2_rn(acc[2 * ng][0], acc[2 * ng][1]);
        *(__half2*)(vp + 512 + c0)      = __floats2half2_rn(acc[2 * ng][2], acc[2 * ng][3]);
        *(__half2*)(vp + c0 + 8)        = __floats2half2_rn(acc[2 * ng + 1][0], acc[2 * ng + 1][1]);
        *(__half2*)(vp + 512 + c0 + 8)  = __floats2half2_rn(acc[2 * ng + 1][2], acc[2 * ng + 1][3]);
    }

    // fused scores: ssrc/sdst for rows r and r+8
    float s0 = 0.f, d0 = 0.f, s1 = 0.f, d1 = 0.f;
#pragma unroll
    for (int ng = 0; ng < 4; ++ng) {
        int c0 = ng * 16 + qc;
        float as0 = avec[c0],      as1 = avec[c0 + 1];
        float as8 = avec[c0 + 8],  as9 = avec[c0 + 9];
        float ad0 = avec[64 + c0], ad1 = avec[64 + c0 + 1];
        float ad8 = avec[64 + c0 + 8], ad9 = avec[64 + c0 + 9];
        s0 += acc[2*ng][0]*as0 + acc[2*ng][1]*as1 + acc[2*ng+1][0]*as8 + acc[2*ng+1][1]*as9;
        d0 += acc[2*ng][0]*ad0 + acc[2*ng][1]*ad1 + acc[2*ng+1][0]*ad8 + acc[2*ng+1][1]*ad9;
        s1 += acc[2*ng][2]*as0 + acc[2*ng][3]*as1 + acc[2*ng+1][2]*as8 + acc[2*ng+1][3]*as9;
        d1 += acc[2*ng][2]*ad0 + acc[2*ng][3]*ad1 + acc[2*ng+1][2]*ad8 + acc[2*ng+1][3]*ad9;
    }
#pragma unroll
    for (int o = 1; o < 4; o <<= 1) {
        s0 += __shfl_xor_sync(0xffffffffu, s0, o);
        d0 += __shfl_xor_sync(0xffffffffu, d0, o);
        s1 += __shfl_xor_sync(0xffffffffu, s1, o);
        d1 += __shfl_xor_sync(0xffffffffu, d1, o);
    }
    if ((lane & 3) == 0) {
        int idx = head * NN + r;
        g_gsh[idx]     = __float2half(expf(-0.8f * s0));
        g_EDh[idx]     = __float2half(expf(d0));
        g_FDh[idx]     = __float2half(expf(0.2f * d0));
        g_gsh[idx + 8] = __float2half(expf(-0.8f * s1));
        g_EDh[idx + 8] = __float2half(expf(d1));
        g_FDh[idx + 8] = __float2half(expf(0.2f * d1));
    }
}

// ---------------- K3: fused attention + last-CTA LayerNorm ----------------
#define SV_BYTES  18432
#define SM_ED     36864
#define SM_ADJ    37888
#define ATTN_SMEM 41984

__global__ __launch_bounds__(128, 2) void k_attn(const float* __restrict__ gamma,
                                                 const float* __restrict__ beta,
                                                 float* __restrict__ out) {
    extern __shared__ char smem[];
    const unsigned sbase = (unsigned)__cvta_generic_to_shared(smem);

    const int t = threadIdx.x;
    const int ig0 = blockIdx.x * ITILE;
    const int h = blockIdx.y;

    const int lane = t & 31;
    const int wid  = t >> 5;
    const int l15  = lane & 15;
    const int lhi  = (lane >> 4) << 3;
    const int qc   = (lane & 3) << 1;
    const int rA   = (wid << 4) + (lane >> 2);    // tile-local row
    const unsigned bz = (lane < 4) ? 0x3C003C00u : 0u;   // ones-column B frag

    const int rbg = h * NN + ig0;
    const __half2 gsA = __half2half2(g_gsh[rbg + rA]);
    const __half2 gsB = __half2half2(g_gsh[rbg + rA + 8]);
    const __half2 gsC = __half2half2(g_gsh[rbg + rA + 64]);
    const __half2 gsD = __half2half2(g_gsh[rbg + rA + 72]);

    // prefetch tile jt2 into buffer buf2
    auto prefetch = [&](int jt2, int buf2) {
        const char* src = (const char*)(g_V + ((size_t)(h * NN) + jt2 * 128 + t) * 64);
        unsigned d = sbase + buf2 * SV_BYTES + t * 144;
#pragma unroll
        for (int i = 0; i < 8; i++) cp16(d + i * 16, src + i * 16);
        cp16(sbase + SM_ADJ + buf2 * 2048 + t * 16,
             (const char*)(g_adjbits + (size_t)(ig0 + t) * 128 + jt2 * 4));
        if (t < 32) {
            int a = t >> 4, c = t & 15;
            const __half* arr = a ? g_FDh : g_EDh;
            cp16(sbase + SM_ED + a * 512 + buf2 * 256 + c * 16,
                 (const char*)(arr + h * NN + jt2 * 128) + c * 16);
        }
        asm volatile("cp.async.commit_group;");
    };

    prefetch(0, 0);

    float acc0[8][4], acc1[8][4], az0[4], az1[4];
#pragma unroll
    for (int x = 0; x < 8; x++)
#pragma unroll
        for (int y = 0; y < 4; y++) { acc0[x][y] = 0.f; acc1[x][y] = 0.f; }
#pragma unroll
    for (int y = 0; y < 4; y++) { az0[y] = 0.f; az1[y] = 0.f; }

    for (int jt = 0; jt < 32; ++jt) {
        const int buf = jt & 1;
        asm volatile("cp.async.wait_group 0;");
        __syncthreads();
        if (jt + 1 < 32) prefetch(jt + 1, buf ^ 1);
        else asm volatile("cp.async.commit_group;");

        const uint4* sAdjB = (const uint4*)(smem + SM_ADJ + buf * 2048);
        const uint4 awA = sAdjB[rA];
        const uint4 awB = sAdjB[rA + 8];
        const uint4 awC = sAdjB[rA + 64];
        const uint4 awD = sAdjB[rA + 72];
        const char* edb = smem + SM_ED + buf * 256;
        const char* fdb = smem + SM_ED + 512 + buf * 256;
        const unsigned vbase = sbase + buf * SV_BYTES;

#pragma unroll
        for (int kt = 0; kt < 8; ++kt) {
            const unsigned o = (kt << 5) + (qc << 1);
            const unsigned edL = *(const unsigned*)(edb + o);
            const unsigned edH = *(const unsigned*)(edb + o + 16);
            const __half2  fdL = *(const __half2*)(fdb + o);
            const __half2  fdH = *(const __half2*)(fdb + o + 16);

            const int sh = ((kt & 1) << 4) + qc;
            const int w4 = kt >> 1;
            const unsigned wA = ((w4 == 0) ? awA.x : (w4 == 1) ? awA.y : (w4 == 2) ? awA.z : awA.w) >> sh;
            const unsigned wB = ((w4 == 0) ? awB.x : (w4 == 1) ? awB.y : (w4 == 2) ? awB.z : awB.w) >> sh;
            const unsigned wC = ((w4 == 0) ? awC.x : (w4 == 1) ? awC.y : (w4 == 2) ? awC.z : awC.w) >> sh;
            const unsigned wD = ((w4 == 0) ? awD.x : (w4 == 1) ? awD.y : (w4 == 2) ? awD.z : awD.w) >> sh;

            const unsigned a0 = wval(edL, gsA, fdL, bmask(wA));
            const unsigned a1 = wval(edL, gsB, fdL, bmask(wB));
            const unsigned a2 = wval(edH, gsA, fdH, bmask(wA >> 8));
            const unsigned a3 = wval(edH, gsB, fdH, bmask(wB >> 8));
            const unsigned c0 = wval(edL, gsC, fdL, bmask(wC));
            const unsigned c1 = wval(edL, gsD, fdL, bmask(wD));
            const unsigned c2 = wval(edH, gsC, fdH, bmask(wC >> 8));
            const unsigned c3 = wval(edH, gsD, fdH, bmask(wD >> 8));

#pragma unroll
            for (int ng = 0; ng < 4; ++ng) {
                unsigned b0, b1, b2, b3;
                unsigned bAddr = vbase + (((kt << 4) + l15) * VPITCH + (ng << 4) + lhi) * 2;
                asm volatile("ldmatrix.sync.aligned.m8n8.x4.trans.shared.b16 {%0,%1,%2,%3}, [%4];\n"
                             : "=r"(b0), "=r"(b1), "=r"(b2), "=r"(b3) : "r"(bAddr));
                mma16816(acc0[2 * ng],     a0, a1, a2, a3, b0, b1);
                mma16816(acc0[2 * ng + 1], a0, a1, a2, a3, b2, b3);
                mma16816(acc1[2 * ng],     c0, c1, c2, c3, b0, b1);
                mma16816(acc1[2 * ng + 1], c0, c1, c2, c3, b2, b3);
            }
            mma16816(az0, a0, a1, a2, a3, bz, bz);
            mma16816(az1, c0, c1, c2, c3, bz, bz);
        }
    } // jt

    // Z broadcast within each 4-lane group (col 0 lives at lane&3==0)
    const float iA = 1.f / __shfl_sync(0xffffffffu, az0[0], lane & 28);
    const float iB = 1.f / __shfl_sync(0xffffffffu, az0[2], lane & 28);
    const float iC = 1.f / __shfl_sync(0xffffffffu, az1[0], lane & 28);
    const float iD = 1.f / __shfl_sync(0xffffffffu, az1[2], lane & 28);

    __half* p0 = g_hph + (size_t)(ig0 + rA) * 512 + (h << 6);
    __half* p2 = g_hph + (size_t)(ig0 + rA + 64) * 512 + (h << 6);
#pragma unroll
    for (int ng = 0; ng < 4; ++ng) {
        const int c0 = ng * 16 + qc;
        *(__half2*)(p0 + c0)            = __floats2half2_rn(acc0[2*ng][0] * iA, acc0[2*ng][1] * iA);
        *(__half2*)(p0 + c0 + 8)        = __floats2half2_rn(acc0[2*ng+1][0] * iA, acc0[2*ng+1][1] * iA);
        *(__half2*)(p0 + 4096 + c0)     = __floats2half2_rn(acc0[2*ng][2] * iB, acc0[2*ng][3] * iB);
        *(__half2*)(p0 + 4096 + c0 + 8) = __floats2half2_rn(acc0[2*ng+1][2] * iB, acc0[2*ng+1][3] * iB);
        *(__half2*)(p2 + c0)            = __floats2half2_rn(acc1[2*ng][0] * iC, acc1[2*ng][1] * iC);
        *(__half2*)(p2 + c0 + 8)        = __floats2half2_rn(acc1[2*ng+1][0] * iC, acc1[2*ng+1][1] * iC);
        *(__half2*)(p2 + 4096 + c0)     = __floats2half2_rn(acc1[2*ng][2] * iD, acc1[2*ng][3] * iD);
        *(__half2*)(p2 + 4096 + c0 + 8) = __floats2half2_rn(acc1[2*ng+1][2] * iD, acc1[2*ng+1][3] * iD);
    }

    // ---- last CTA of this i-tile (across heads) does the LayerNorm ----
    __threadfence();
    __shared__ int s_last;
    if (t == 0) s_last = (atomicAdd(&g_cnt[blockIdx.x], 1) == HEADS - 1);
    __syncthreads();
    if (s_last) {
        const float2 gm = ((const float2*)gamma)[lane];
        const float2 bt = ((const float2*)beta)[lane];
        for (int it = 0; it < 32; ++it) {
            const int row = ig0 + wid * 32 + it;
            const __half2* hp = (const __half2*)(g_hph + (size_t)row * 512);
            float2 m = make_float2(0.f, 0.f);
#pragma unroll
            for (int hh = 0; hh < HEADS; hh++) {
                float2 v = __half22float2(hp[hh * 32 + lane]);
                m.x += v.x; m.y += v.y;
            }
            m.x *= 0.125f; m.y *= 0.125f;
            float s = m.x + m.y;
#pragma unroll
            for (int o = 16; o > 0; o >>= 1) s += __shfl_xor_sync(0xffffffffu, s, o);
            const float mu = s * (1.f / 64.f);
            const float dx = m.x - mu, dy = m.y - mu;
            float q = dx * dx + dy * dy;
#pragma unroll
            for (int o = 16; o > 0; o >>= 1) q += __shfl_xor_sync(0xffffffffu, q, o);
            const float rs = rsqrtf(q * (1.f / 64.f) + 1e-5f);
            ((float2*)(out + (size_t)row * 64))[lane] =
                make_float2(dx * rs * gm.x + bt.x, dy * rs * gm.y + bt.y);
        }
        if (t == 0) g_cnt[blockIdx.x] = 0;   // reset for next graph replay
    }
}

// ---------------- launch: 3 kernels, pack forked parallel with gemm ----------------
extern "C" void kernel_launch(void* const* d_in, const int* in_sizes, int n_in,
                              void* d_out, int out_size) {
    const float* hmat  = (const float*)d_in[0];
    const int*   adj   = (const int*)  d_in[1];
    const float* W     = (const float*)d_in[2];
    const float* avec  = (const float*)d_in[3];
    const float* gamma = (const float*)d_in[4];
    const float* beta  = (const float*)d_in[5];
    float* out = (float*)d_out;

    static cudaStream_t s_side = [] {
        cudaStream_t s;
        cudaStreamCreateWithFlags(&s, cudaStreamNonBlocking);
        return s;
    }();
    static cudaEvent_t ev_fork = [] {
        cudaEvent_t e;
        cudaEventCreateWithFlags(&e, cudaEventDisableTiming);
        return e;
    }();
    static cudaEvent_t ev_join = [] {
        cudaEvent_t e;
        cudaEventCreateWithFlags(&e, cudaEventDisableTiming);
        return e;
    }();

    cudaEventRecord(ev_fork, 0);
    cudaStreamWaitEvent(s_side, ev_fork, 0);
    k_pack_adj<<<(NN * NN) / 256, 256, 0, s_side>>>(adj);
    cudaEventRecord(ev_join, s_side);

    k_gemm_ht<<<dim3(8, 32), 256>>>(hmat, W, avec);

    cudaStreamWaitEvent(0, ev_join, 0);
    k_attn<<<dim3(NN / ITILE, HEADS), 128, ATTN_SMEM>>>(gamma, beta, out);
}

// round 17
// speedup vs baseline: 1.3132x; 1.3132x over previous
#include <cuda_runtime.h>
#include <cuda_fp16.h>

#define NN      4096
#define HEADS   8
#define OUT_F   64
#define ITILE   128
#define VPITCH  72     // halfs per sV row (144B)

__device__ __half   g_hh[NN * 256];
__device__ __half   g_Wh[256 * 512];
__device__ __half   g_V[(size_t)HEADS * NN * OUT_F];
__device__ __half   g_gsh [HEADS * NN];
__device__ __half   g_EDh [HEADS * NN];
__device__ __half   g_FDh [HEADS * NN];
__device__ unsigned g_adjbits[NN * (NN / 32)];
__device__ __half   g_hph[(size_t)NN * 512];

__device__ __forceinline__ void cp16(unsigned dst, const void* src) {
    asm volatile("cp.async.cg.shared.global [%0], [%1], 16;"
                 :: "r"(dst), "l"(__cvta_generic_to_global(src)));
}
__device__ __forceinline__ __half2 u2h2(unsigned x) { return *reinterpret_cast<__half2*>(&x); }
__device__ __forceinline__ unsigned h22u(__half2 x) { return *reinterpret_cast<unsigned*>(&x); }
// 2 adjacency bits -> half2 keep-mask
__device__ __forceinline__ unsigned bmask(unsigned b) {
    return ((b & 1u) * 0xFFFFu) | ((b & 2u) * 0x7FFF8000u);
}
// w = adj ? max(ed, gs*fd) : 0   (lrelu(x)=max(x,0.2x) => exp factorization)
__device__ __forceinline__ unsigned wval(unsigned ed, __half2 gs, __half2 fd, unsigned am) {
    return h22u(__hmax2(u2h2(ed), __hmul2(gs, fd))) & am;
}
__device__ __forceinline__ void mma16816(float* c, unsigned a0, unsigned a1,
                                         unsigned a2, unsigned a3,
                                         unsigned b0, unsigned b1) {
    asm volatile("mma.sync.aligned.m16n8k16.row.col.f32.f16.f16.f32 "
                 "{%0,%1,%2,%3}, {%4,%5,%6,%7}, {%8,%9}, {%0,%1,%2,%3};\n"
                 : "+f"(c[0]), "+f"(c[1]), "+f"(c[2]), "+f"(c[3])
                 : "r"(a0), "r"(a1), "r"(a2), "r"(a3), "r"(b0), "r"(b1));
}

// ---------------- K0: pack adjacency into bitmask (vectorized, 1 word/thread) ----------------
__global__ void k_pack_adj(const int* __restrict__ adj) {
    const size_t w = (size_t)blockIdx.x * 256 + threadIdx.x;   // output word index
    const int4* a = (const int4*)adj + w * 8;
    int4 v[8];
#pragma unroll
    for (int i = 0; i < 8; i++) v[i] = a[i];
    unsigned m = 0;
#pragma unroll
    for (int i = 0; i < 8; i++) {
        m |= (v[i].x > 0 ? 1u : 0u) << (4 * i);
        m |= (v[i].y > 0 ? 1u : 0u) << (4 * i + 1);
        m |= (v[i].z > 0 ? 1u : 0u) << (4 * i + 2);
        m |= (v[i].w > 0 ? 1u : 0u) << (4 * i + 3);
    }
    g_adjbits[w] = m;
}

// ---------------- K0b: convert h, W to half ----------------
__global__ void k_cvt(const float* __restrict__ hmat, const float* __restrict__ W) {
    int i = blockIdx.x * 256 + threadIdx.x;
    if (i < 262144) {
        float4 v = ((const float4*)hmat)[i];
        ((__half2*)g_hh)[2 * i]     = __floats2half2_rn(v.x, v.y);
        ((__half2*)g_hh)[2 * i + 1] = __floats2half2_rn(v.z, v.w);
    } else {
        int j = i - 262144;
        float4 v = ((const float4*)W)[j];
        ((__half2*)g_Wh)[2 * j]     = __floats2half2_rn(v.x, v.y);
        ((__half2*)g_Wh)[2 * j + 1] = __floats2half2_rn(v.z, v.w);
    }
}

// ---------------- K1: ht = h @ W (fp16 TC) -> g_V, + fused scores ----------------
__global__ __launch_bounds__(256) void k_gemm_ht(const float* __restrict__ avec) {
    __shared__ __align__(16) __half sA[128 * 72];
    __shared__ __align__(16) __half sB[64 * 72];
    const int t = threadIdx.x, lane = t & 31, wid = t >> 5;
    const int head = blockIdx.x, rowBase = blockIdx.y * 128;
    const int l15 = lane & 15, lhi = (lane >> 4) << 3, qc = (lane & 3) << 1;
    const unsigned sAb = (unsigned)__cvta_generic_to_shared(sA);
    const unsigned sBb = (unsigned)__cvta_generic_to_shared(sB);

    float acc[8][4];
#pragma unroll
    for (int x = 0; x < 8; x++)
#pragma unroll
        for (int y = 0; y < 4; y++) acc[x][y] = 0.f;

    for (int k0 = 0; k0 < 256; k0 += 64) {
        __syncthreads();
        {
            const char* src = (const char*)(g_hh + (size_t)(rowBase + (t >> 1)) * 256 + k0 + (t & 1) * 32);
            unsigned d = sAb + ((t >> 1) * 72 + (t & 1) * 32) * 2;
            cp16(d, src); cp16(d + 16, src + 16); cp16(d + 32, src + 32); cp16(d + 48, src + 48);
        }
        if (t < 128) {
            const char* src = (const char*)(g_Wh + (size_t)(k0 + (t >> 1)) * 512 + head * 64 + (t & 1) * 32);
            unsigned d = sBb + ((t >> 1) * 72 + (t & 1) * 32) * 2;
            cp16(d, src); cp16(d + 16, src + 16); cp16(d + 32, src + 32); cp16(d + 48, src + 48);
        }
        asm volatile("cp.async.commit_group;");
        asm volatile("cp.async.wait_group 0;");
        __syncthreads();
#pragma unroll
        for (int kt = 0; kt < 4; ++kt) {
            unsigned a0, a1, a2, a3;
            unsigned aAddr = sAb + (((wid << 4) + l15) * 72 + (kt << 4) + lhi) * 2;
            asm volatile("ldmatrix.sync.aligned.m8n8.x4.shared.b16 {%0,%1,%2,%3}, [%4];\n"
                         : "=r"(a0), "=r"(a1), "=r"(a2), "=r"(a3) : "r"(aAddr));
#pragma unroll
            for (int ng = 0; ng < 4; ++ng) {
                unsigned b0, b1, b2, b3;
                unsigned bAddr = sBb + (((kt << 4) + l15) * 72 + (ng << 4) + lhi) * 2;
                asm volatile("ldmatrix.sync.aligned.m8n8.x4.trans.shared.b16 {%0,%1,%2,%3}, [%4];\n"
                             : "=r"(b0), "=r"(b1), "=r"(b2), "=r"(b3) : "r"(bAddr));
                mma16816(acc[2 * ng],     a0, a1, a2, a3, b0, b1);
                mma16816(acc[2 * ng + 1], a0, a1, a2, a3, b2, b3);
            }
        }
    }
    const int r = rowBase + (wid << 4) + (lane >> 2);
    __half* vp = g_V + (size_t)head * NN * 64 + (size_t)r * 64;
#pragma unroll
    for (int ng = 0; ng < 4; ++ng) {
        int c0 = ng * 16 + qc;
        *(__half2*)(vp + c0)            = __floats2half2_rn(acc[2 * ng][0], acc[2 * ng][1]);
        *(__half2*)(vp + 512 + c0)      = __floats2half2_rn(acc[2 * ng][2], acc[2 * ng][3]);
        *(__half2*)(vp + c0 + 8)        = __floats2half2_rn(acc[2 * ng + 1][0], acc[2 * ng + 1][1]);
        *(__half2*)(vp + 512 + c0 + 8)  = __floats2half2_rn(acc[2 * ng + 1][2], acc[2 * ng + 1][3]);
    }

    // fused scores: ssrc/sdst for rows r and r+8
    float s0 = 0.f, d0 = 0.f, s1 = 0.f, d1 = 0.f;
#pragma unroll
    for (int ng = 0; ng < 4; ++ng) {
        int c0 = ng * 16 + qc;
        float as0 = avec[c0],      as1 = avec[c0 + 1];
        float as8 = avec[c0 + 8],  as9 = avec[c0 + 9];
        float ad0 = avec[64 + c0], ad1 = avec[64 + c0 + 1];
        float ad8 = avec[64 + c0 + 8], ad9 = avec[64 + c0 + 9];
        s0 += acc[2*ng][0]*as0 + acc[2*ng][1]*as1 + acc[2*ng+1][0]*as8 + acc[2*ng+1][1]*as9;
        d0 += acc[2*ng][0]*ad0 + acc[2*ng][1]*ad1 + acc[2*ng+1][0]*ad8 + acc[2*ng+1][1]*ad9;
        s1 += acc[2*ng][2]*as0 + acc[2*ng][3]*as1 + acc[2*ng+1][2]*as8 + acc[2*ng+1][3]*as9;
        d1 += acc[2*ng][2]*ad0 + acc[2*ng][3]*ad1 + acc[2*ng+1][2]*ad8 + acc[2*ng+1][3]*ad9;
    }
#pragma unroll
    for (int o = 1; o < 4; o <<= 1) {
        s0 += __shfl_xor_sync(0xffffffffu, s0, o);
        d0 += __shfl_xor_sync(0xffffffffu, d0, o);
        s1 += __shfl_xor_sync(0xffffffffu, s1, o);
        d1 += __shfl_xor_sync(0xffffffffu, d1, o);
    }
    if ((lane & 3) == 0) {
        int idx = head * NN + r;
        g_gsh[idx]     = __float2half(expf(-0.8f * s0));
        g_EDh[idx]     = __float2half(expf(d0));
        g_FDh[idx]     = __float2half(expf(0.2f * d0));
        g_gsh[idx + 8] = __float2half(expf(-0.8f * s1));
        g_EDh[idx + 8] = __float2half(expf(d1));
        g_FDh[idx + 8] = __float2half(expf(0.2f * d1));
    }
}

// ---------------- K3: fused attention, one CTA per (itile, head), full j ----------------
#define SV_BYTES  18432
#define SM_ED     36864
#define SM_ADJ    37888
#define ATTN_SMEM 41984

__global__ __launch_bounds__(128, 2) void k_attn() {
    extern __shared__ char smem[];
    const unsigned sbase = (unsigned)__cvta_generic_to_shared(smem);

    const int t = threadIdx.x;
    const int ig0 = blockIdx.x * ITILE;
    const int h = blockIdx.y;

    const int lane = t & 31;
    const int wid  = t >> 5;
    const int l15  = lane & 15;
    const int lhi  = (lane >> 4) << 3;
    const int qc   = (lane & 3) << 1;
    const int rA   = (wid << 4) + (lane >> 2);    // tile-local row
    const unsigned bz = (lane < 4) ? 0x3C003C00u : 0u;   // ones-column B frag

    const int rbg = h * NN + ig0;
    const __half2 gsA = __half2half2(g_gsh[rbg + rA]);
    const __half2 gsB = __half2half2(g_gsh[rbg + rA + 8]);
    const __half2 gsC = __half2half2(g_gsh[rbg + rA + 64]);
    const __half2 gsD = __half2half2(g_gsh[rbg + rA + 72]);

    // prefetch tile jt2 into buffer buf2
    auto prefetch = [&](int jt2, int buf2) {
        const char* src = (const char*)(g_V + ((size_t)(h * NN) + jt2 * 128 + t) * 64);
        unsigned d = sbase + buf2 * SV_BYTES + t * 144;
#pragma unroll
        for (int i = 0; i < 8; i++) cp16(d + i * 16, src + i * 16);
        cp16(sbase + SM_ADJ + buf2 * 2048 + t * 16,
             (const char*)(g_adjbits + (size_t)(ig0 + t) * 128 + jt2 * 4));
        if (t < 32) {
            int a = t >> 4, c = t & 15;
            const __half* arr = a ? g_FDh : g_EDh;
            cp16(sbase + SM_ED + a * 512 + buf2 * 256 + c * 16,
                 (const char*)(arr + h * NN + jt2 * 128) + c * 16);
        }
        asm volatile("cp.async.commit_group;");
    };

    prefetch(0, 0);

    float acc0[8][4], acc1[8][4], az0[4], az1[4];
#pragma unroll
    for (int x = 0; x < 8; x++)
#pragma unroll
        for (int y = 0; y < 4; y++) { acc0[x][y] = 0.f; acc1[x][y] = 0.f; }
#pragma unroll
    for (int y = 0; y < 4; y++) { az0[y] = 0.f; az1[y] = 0.f; }

    for (int jt = 0; jt < 32; ++jt) {
        const int buf = jt & 1;
        asm volatile("cp.async.wait_group 0;");
        __syncthreads();
        if (jt + 1 < 32) prefetch(jt + 1, buf ^ 1);
        else asm volatile("cp.async.commit_group;");

        const uint4* sAdjB = (const uint4*)(smem + SM_ADJ + buf * 2048);
        const uint4 awA = sAdjB[rA];
        const uint4 awB = sAdjB[rA + 8];
        const uint4 awC = sAdjB[rA + 64];
        const uint4 awD = sAdjB[rA + 72];
        const char* edb = smem + SM_ED + buf * 256;
        const char* fdb = smem + SM_ED + 512 + buf * 256;
        const unsigned vbase = sbase + buf * SV_BYTES;

#pragma unroll
        for (int kt = 0; kt < 8; ++kt) {
            const unsigned o = (kt << 5) + (qc << 1);
            const unsigned edL = *(const unsigned*)(edb + o);
            const unsigned edH = *(const unsigned*)(edb + o + 16);
            const __half2  fdL = *(const __half2*)(fdb + o);
            const __half2  fdH = *(const __half2*)(fdb + o + 16);

            const int sh = ((kt & 1) << 4) + qc;
            const int w4 = kt >> 1;
            const unsigned wA = ((w4 == 0) ? awA.x : (w4 == 1) ? awA.y : (w4 == 2) ? awA.z : awA.w) >> sh;
            const unsigned wB = ((w4 == 0) ? awB.x : (w4 == 1) ? awB.y : (w4 == 2) ? awB.z : awB.w) >> sh;
            const unsigned wC = ((w4 == 0) ? awC.x : (w4 == 1) ? awC.y : (w4 == 2) ? awC.z : awC.w) >> sh;
            const unsigned wD = ((w4 == 0) ? awD.x : (w4 == 1) ? awD.y : (w4 == 2) ? awD.z : awD.w) >> sh;

            const unsigned a0 = wval(edL, gsA, fdL, bmask(wA));
            const unsigned a1 = wval(edL, gsB, fdL, bmask(wB));
            const unsigned a2 = wval(edH, gsA, fdH, bmask(wA >> 8));
            const unsigned a3 = wval(edH, gsB, fdH, bmask(wB >> 8));
            const unsigned c0 = wval(edL, gsC, fdL, bmask(wC));
            const unsigned c1 = wval(edL, gsD, fdL, bmask(wD));
            const unsigned c2 = wval(edH, gsC, fdH, bmask(wC >> 8));
            const unsigned c3 = wval(edH, gsD, fdH, bmask(wD >> 8));

#pragma unroll
            for (int ng = 0; ng < 4; ++ng) {
                unsigned b0, b1, b2, b3;
                unsigned bAddr = vbase + (((kt << 4) + l15) * VPITCH + (ng << 4) + lhi) * 2;
                asm volatile("ldmatrix.sync.aligned.m8n8.x4.trans.shared.b16 {%0,%1,%2,%3}, [%4];\n"
                             : "=r"(b0), "=r"(b1), "=r"(b2), "=r"(b3) : "r"(bAddr));
                mma16816(acc0[2 * ng],     a0, a1, a2, a3, b0, b1);
                mma16816(acc0[2 * ng + 1], a0, a1, a2, a3, b2, b3);
                mma16816(acc1[2 * ng],     c0, c1, c2, c3, b0, b1);
                mma16816(acc1[2 * ng + 1], c0, c1, c2, c3, b2, b3);
            }
            mma16816(az0, a0, a1, a2, a3, bz, bz);
            mma16816(az1, c0, c1, c2, c3, bz, bz);
        }
    } // jt

    // Z broadcast within each 4-lane group (col 0 lives at lane&3==0)
    const float iA = 1.f / __shfl_sync(0xffffffffu, az0[0], lane & 28);
    const float iB = 1.f / __shfl_sync(0xffffffffu, az0[2], lane & 28);
    const float iC = 1.f / __shfl_sync(0xffffffffu, az1[0], lane & 28);
    const float iD = 1.f / __shfl_sync(0xffffffffu, az1[2], lane & 28);

    __half* p0 = g_hph + (size_t)(ig0 + rA) * 512 + (h << 6);
    __half* p2 = g_hph + (size_t)(ig0 + rA + 64) * 512 + (h << 6);
#pragma unroll
    for (int ng = 0; ng < 4; ++ng) {
        const int c0 = ng * 16 + qc;
        *(__half2*)(p0 + c0)            = __floats2half2_rn(acc0[2*ng][0] * iA, acc0[2*ng][1] * iA);
        *(__half2*)(p0 + c0 + 8)        = __floats2half2_rn(acc0[2*ng+1][0] * iA, acc0[2*ng+1][1] * iA);
        *(__half2*)(p0 + 4096 + c0)     = __floats2half2_rn(acc0[2*ng][2] * iB, acc0[2*ng][3] * iB);
        *(__half2*)(p0 + 4096 + c0 + 8) = __floats2half2_rn(acc0[2*ng+1][2] * iB, acc0[2*ng+1][3] * iB);
        *(__half2*)(p2 + c0)            = __floats2half2_rn(acc1[2*ng][0] * iC, acc1[2*ng][1] * iC);
        *(__half2*)(p2 + c0 + 8)        = __floats2half2_rn(acc1[2*ng+1][0] * iC, acc1[2*ng+1][1] * iC);
        *(__half2*)(p2 + 4096 + c0)     = __floats2half2_rn(acc1[2*ng][2] * iD, acc1[2*ng][3] * iD);
        *(__half2*)(p2 + 4096 + c0 + 8) = __floats2half2_rn(acc1[2*ng+1][2] * iD, acc1[2*ng+1][3] * iD);
    }
}

// ---------------- K4: head-mean + LayerNorm (one warp per row, shuffle-only) ----------------
__global__ __launch_bounds__(256) void k_finalize(const float* __restrict__ gamma,
                                                  const float* __restrict__ beta,
                                                  float* __restrict__ out) {
    const int row = blockIdx.x * 8 + (threadIdx.x >> 5);
    const int lane = threadIdx.x & 31;
    const __half2* hp = (const __half2*)(g_hph + (size_t)row * 512);

    float2 m = make_float2(0.f, 0.f);
#pragma unroll
    for (int h = 0; h < HEADS; h++) {
        float2 v = __half22float2(hp[h * 32 + lane]);
        m.x += v.x; m.y += v.y;
    }
    m.x *= 0.125f; m.y *= 0.125f;

    float s = m.x + m.y;
#pragma unroll
    for (int o = 16; o > 0; o >>= 1) s += __shfl_xor_sync(0xffffffffu, s, o);
    const float mu = s * (1.f / 64.f);

    const float dx = m.x - mu, dy = m.y - mu;
    float q = dx * dx + dy * dy;
#pragma unroll
    for (int o = 16; o > 0; o >>= 1) q += __shfl_xor_sync(0xffffffffu, q, o);
    const float rs = rsqrtf(q * (1.f / 64.f) + 1e-5f);

    const float2 gm = ((const float2*)gamma)[lane];
    const float2 bt = ((const float2*)beta)[lane];
    ((float2*)(out + (size_t)row * 64))[lane] =
        make_float2(dx * rs * gm.x + bt.x, dy * rs * gm.y + bt.y);
}

// ---------------- launch: fork pack_adj parallel with cvt->gemm ----------------
extern "C" void kernel_launch(void* const* d_in, const int* in_sizes, int n_in,
                              void* d_out, int out_size) {
    const float* hmat  = (const float*)d_in[0];
    const int*   adj   = (const int*)  d_in[1];
    const float* W     = (const float*)d_in[2];
    const float* avec  = (const float*)d_in[3];
    const float* gamma = (const float*)d_in[4];
    const float* beta  = (const float*)d_in[5];
    float* out = (float*)d_out;

    static cudaStream_t s_side = [] {
        cudaStream_t s;
        cudaStreamCreateWithFlags(&s, cudaStreamNonBlocking);
        return s;
    }();
    static cudaEvent_t ev_fork = [] {
        cudaEvent_t e;
        cudaEventCreateWithFlags(&e, cudaEventDisableTiming);
        return e;
    }();
    static cudaEvent_t ev_join = [] {
        cudaEvent_t e;
        cudaEventCreateWithFlags(&e, cudaEventDisableTiming);
        return e;
    }();

    cudaEventRecord(ev_fork, 0);
    cudaStreamWaitEvent(s_side, ev_fork, 0);
    k_pack_adj<<<2048, 256, 0, s_side>>>(adj);
    cudaEventRecord(ev_join, s_side);

    k_cvt<<<1152, 256>>>(hmat, W);
    k_gemm_ht<<<dim3(8, 32), 256>>>(avec);

    cudaStreamWaitEvent(0, ev_join, 0);
    k_attn<<<dim3(NN / ITILE, HEADS), 128, ATTN_SMEM>>>();
    k_finalize<<<NN / 8, 256>>>(gamma, beta, out);
}